// round 11
// baseline (speedup 1.0000x reference)
#include <cuda_runtime.h>
#include <cuda_fp16.h>
#include <math.h>

#define NNODES 50000
#define DIM 128
#define MEDGE 800000
#define NWARPBLK 8
#define NODE_BLKS ((NNODES + NWARPBLK - 1) / NWARPBLK)   // 6250
#define SCAN_BS 1024
#define SCAN_NB ((NNODES + SCAN_BS - 1) / SCAN_BS)        // 49

// ------------------------- scratch (static device memory) -------------------
__device__ float g_X[NNODES * DIM];     // raw routing output (layer 2 only)
__device__ float g_XN[NNODES * DIM];    // normalized x, fp32 (self term)
__device__ uint2 g_XNHA[NNODES * 32];   // normalized x fp16, layer-1 gathers
__device__ uint2 g_XNHB[NNODES * 32];   // normalized x fp16, layer-2 gathers
__device__ float g_S[NNODES * 32];      // per-node s vector
__device__ int   g_deg[NNODES];
__device__ int   g_tmp[NNODES];
__device__ int   g_rowoff[NNODES + 1];
__device__ int   g_cursor[NNODES + 1];
__device__ int   g_csrc[MEDGE];
__device__ int   g_bsum[64];
__device__ int   g_is64;

__device__ __forceinline__ float ex2(float x) {
    float r;
    asm("ex2.approx.f32 %0, %1;" : "=f"(r) : "f"(x));
    return r;
}
__device__ __forceinline__ unsigned long long pack2(float lo, float hi) {
    unsigned long long r;
    asm("mov.b64 %0, {%1, %2};" : "=l"(r) : "f"(lo), "f"(hi));
    return r;
}
__device__ __forceinline__ float2 unpack2(unsigned long long p) {
    float lo, hi;
    asm("mov.b64 {%0, %1}, %2;" : "=f"(lo), "=f"(hi) : "l"(p));
    return make_float2(lo, hi);
}
__device__ __forceinline__ unsigned long long ffma2(unsigned long long a,
                                                    unsigned long long b,
                                                    unsigned long long c) {
    unsigned long long d;
    asm("fma.rn.f32x2 %0, %1, %2, %3;" : "=l"(d) : "l"(a), "l"(b), "l"(c));
    return d;
}

// ------------------------- edge index dtype handling ------------------------
__global__ void k_detect(const int* __restrict__ ei) {
    __shared__ int nz;
    if (threadIdx.x == 0) nz = 0;
    __syncthreads();
    if (ei[2 * threadIdx.x + 1] != 0) atomicOr(&nz, 1);
    __syncthreads();
    if (threadIdx.x == 0) g_is64 = nz ? 0 : 1;
}

__device__ __forceinline__ int load_idx(const void* ei, long long pos, int is64) {
    if (is64) return (int)((const long long*)ei)[pos];
    return ((const int*)ei)[pos];
}

// ------------------------- CSR build ----------------------------------------
__global__ void k_zero() {
    int i = blockIdx.x * blockDim.x + threadIdx.x;
    if (i < NNODES) g_deg[i] = 0;
}

__global__ void k_hist(const void* __restrict__ ei) {
    int e = blockIdx.x * blockDim.x + threadIdx.x;
    if (e < MEDGE) {
        int t = load_idx(ei, (long long)MEDGE + e, g_is64);
        atomicAdd(&g_deg[t], 1);
    }
}

__global__ void k_scan1() {
    __shared__ int wsum[32];
    const unsigned full = 0xffffffffu;
    int i = blockIdx.x * SCAN_BS + threadIdx.x;
    int lane = threadIdx.x & 31;
    int wid = threadIdx.x >> 5;
    int s = (i < NNODES) ? g_deg[i] : 0;
#pragma unroll
    for (int o = 1; o < 32; o <<= 1) {
        int t = __shfl_up_sync(full, s, o);
        if (lane >= o) s += t;
    }
    if (lane == 31) wsum[wid] = s;
    __syncthreads();
    if (wid == 0) {
        int w = wsum[lane];
#pragma unroll
        for (int o = 1; o < 32; o <<= 1) {
            int t = __shfl_up_sync(full, w, o);
            if (lane >= o) w += t;
        }
        wsum[lane] = w;
    }
    __syncthreads();
    int total = s + (wid ? wsum[wid - 1] : 0);
    if (i < NNODES) g_tmp[i] = total;
    if (threadIdx.x == SCAN_BS - 1) g_bsum[blockIdx.x] = total;
}

__global__ void k_scan3() {
    __shared__ int bx[SCAN_NB];
    if (threadIdx.x < SCAN_NB) bx[threadIdx.x] = g_bsum[threadIdx.x];
    __syncthreads();
    if (threadIdx.x == 0) {
        int run = 0;
#pragma unroll
        for (int b = 0; b < SCAN_NB; b++) { int t = bx[b]; bx[b] = run; run += t; }
    }
    __syncthreads();
    int i = blockIdx.x * blockDim.x + threadIdx.x;
    if (i < NNODES) {
        int inc = g_tmp[i] + bx[i >> 10];
        g_rowoff[i + 1] = inc;
        g_cursor[i + 1] = inc;
        if (i == 0) { g_rowoff[0] = 0; g_cursor[0] = 0; }
    }
}

__global__ void k_fill(const void* __restrict__ ei) {
    int e = blockIdx.x * blockDim.x + threadIdx.x;
    if (e < MEDGE) {
        int is64 = g_is64;
        int t = load_idx(ei, (long long)MEDGE + e, is64);
        int s = load_idx(ei, e, is64);
        int pos = atomicAdd(&g_cursor[t], 1);
        g_csrc[pos] = s;
    }
}

// ------------------------- GEMM (rows x 128) @ (128 x 128) + bias -----------
// NORM_EPI: channel-normalize each output row, write XN (fp32), XNHA (fp16), S.
// COPY_A: stream the smem A tile to Acopy.
template <bool NORM_EPI, bool COPY_A>
__device__ __forceinline__ void gemm_body(const float* __restrict__ A,
                                          const float* __restrict__ W,
                                          const float* __restrict__ bias,
                                          float* __restrict__ C,
                                          float* __restrict__ Acopy, int nrows) {
    extern __shared__ float sh[];
    float4* Ws4 = (float4*)sh;                 // 128x128 floats
    float4* As4 = (float4*)(sh + DIM * DIM);   // 64x128 floats
    int tid = threadIdx.x;            // 256 threads
    int tx = tid & 31;                // column group (4 cols)
    int ty = tid >> 5;                // row group (8 rows) == warp id
    int row0 = blockIdx.x * 64;
    const unsigned full = 0xffffffffu;

    const float4* W4 = (const float4*)W;
#pragma unroll
    for (int i = 0; i < 16; i++) Ws4[tid + i * 256] = W4[tid + i * 256];
#pragma unroll
    for (int i = 0; i < 8; i++) {
        int idx = tid + i * 256;
        int r = idx >> 5;
        float4 v = make_float4(0.f, 0.f, 0.f, 0.f);
        if (row0 + r < nrows) v = ((const float4*)A)[(size_t)(row0 + r) * 32 + (idx & 31)];
        As4[idx] = v;
    }
    __syncthreads();

    float4 acc[8];
#pragma unroll
    for (int r = 0; r < 8; r++) acc[r] = make_float4(0.f, 0.f, 0.f, 0.f);

#pragma unroll
    for (int k4 = 0; k4 < 32; k4++) {
        float4 w0 = Ws4[(k4 * 4 + 0) * 32 + tx];
        float4 w1 = Ws4[(k4 * 4 + 1) * 32 + tx];
        float4 w2 = Ws4[(k4 * 4 + 2) * 32 + tx];
        float4 w3 = Ws4[(k4 * 4 + 3) * 32 + tx];
#pragma unroll
        for (int r = 0; r < 8; r++) {
            float4 a = As4[(ty * 8 + r) * 32 + k4];
            acc[r].x = fmaf(a.x, w0.x, fmaf(a.y, w1.x, fmaf(a.z, w2.x, fmaf(a.w, w3.x, acc[r].x))));
            acc[r].y = fmaf(a.x, w0.y, fmaf(a.y, w1.y, fmaf(a.z, w2.y, fmaf(a.w, w3.y, acc[r].y))));
            acc[r].z = fmaf(a.x, w0.z, fmaf(a.y, w1.z, fmaf(a.z, w2.z, fmaf(a.w, w3.z, acc[r].z))));
            acc[r].w = fmaf(a.x, w0.w, fmaf(a.y, w1.w, fmaf(a.z, w2.w, fmaf(a.w, w3.w, acc[r].w))));
        }
    }

    float4 b4 = ((const float4*)bias)[tx];
#pragma unroll
    for (int r = 0; r < 8; r++) {
        int row = row0 + ty * 8 + r;
        float4 o = acc[r];
        o.x += b4.x; o.y += b4.y; o.z += b4.z; o.w += b4.w;
        if (NORM_EPI) {
            // channel norm: lanes 8c..8c+7 hold channel c of this row
            float ss = o.x * o.x + o.y * o.y + o.z * o.z + o.w * o.w;
            ss += __shfl_xor_sync(full, ss, 1);
            ss += __shfl_xor_sync(full, ss, 2);
            ss += __shfl_xor_sync(full, ss, 4);
            float inv = 1.0f / fmaxf(sqrtf(ss), 1e-12f);
            o.x *= inv; o.y *= inv; o.z *= inv; o.w *= inv;
            if (row < nrows) {
                ((float4*)g_XN)[(size_t)row * 32 + tx] = o;
                __half2 h0 = __floats2half2_rn(o.x, o.y);
                __half2 h1 = __floats2half2_rn(o.z, o.w);
                uint2 pk;
                pk.x = *reinterpret_cast<unsigned int*>(&h0);
                pk.y = *reinterpret_cast<unsigned int*>(&h1);
                g_XNHA[(size_t)row * 32 + tx] = pk;
                g_S[(size_t)row * 32 + tx] = o.x + o.y + o.z + o.w;
            }
        } else {
            if (row < nrows) ((float4*)C)[(size_t)row * 32 + tx] = o;
        }
    }

    if (COPY_A) {
#pragma unroll
        for (int i = 0; i < 8; i++) {
            int idx = tid + i * 256;
            int r = idx >> 5;
            if (row0 + r < nrows)
                ((float4*)Acopy)[(size_t)(row0 + r) * 32 + (idx & 31)] = As4[idx];
        }
    }
}

__global__ void k_gemm_in(const float* __restrict__ A, const float* __restrict__ W,
                          const float* __restrict__ b) {
    gemm_body<true, false>(A, W, b, nullptr, nullptr, NNODES);
}

__global__ void k_gemm_out(const float* __restrict__ W, const float* __restrict__ b,
                           float* __restrict__ C, float* __restrict__ Xout) {
    gemm_body<false, true>(g_X, W, b, C, Xout, NNODES);
}

// ------------------------- routing iteration -------------------------------
// One warp per target node, 4 edges per iteration (8 lanes/edge),
// software-pipelined, packed f32x2 math, lane-owned-channel softmax.
// GATHER buffer is BUF (A for layer 1, B for layer 2).
// MODE 0: write S only. MODE 1: layer boundary — write XN/XNHB/S (fused norm;
//         writes go to the OTHER fp16 buffer to avoid the gather race).
// MODE 2: final — write raw c to g_X.
template <int MODE, int BUF>
__global__ void k_edge() {
    int v = (blockIdx.x * blockDim.x + threadIdx.x) >> 5;
    int lane = threadIdx.x & 31;
    if (v >= NNODES) return;
    int grp = lane >> 3;          // edge slot 0..3
    int sub = lane & 7;           // lane within edge group
    int half = sub & 1;           // which 16-element half of the channel
    const unsigned full = 0xffffffffu;
    const float LOG2E = 1.4426950408889634f;

    // s values (packed f32x2), pre-scaled by log2(e)
    unsigned long long sv[8];
    {
        const float4* srow = (const float4*)(g_S + (size_t)v * 32 + half * 16);
#pragma unroll
        for (int q = 0; q < 4; q++) {
            float4 t = srow[q];
            sv[2 * q + 0] = pack2(t.x * LOG2E, t.y * LOG2E);
            sv[2 * q + 1] = pack2(t.z * LOG2E, t.w * LOG2E);
        }
    }

    // accumulator (packed): group 0 seeds with the self term x_norm[v]
    unsigned long long acc2[8];
    if (grp == 0) {
        const float4* xnrow = (const float4*)(g_XN + (size_t)v * DIM + sub * 16);
#pragma unroll
        for (int q = 0; q < 4; q++) {
            float4 t = xnrow[q];
            acc2[2 * q + 0] = pack2(t.x, t.y);
            acc2[2 * q + 1] = pack2(t.z, t.w);
        }
    } else {
#pragma unroll
        for (int j = 0; j < 8; j++) acc2[j] = 0ull;
    }

    int e0 = g_rowoff[v];
    int e1 = g_rowoff[v + 1];
    int niter = (e1 - e0 + 3) >> 2;
    const uint4* XNH4 = (const uint4*)(BUF == 0 ? g_XNHA : g_XNHB);

    if (niter > 0) {
        // prefetch iteration 0 (all lanes load same 4 consecutive ints: 1 line)
        int u = __ldg(&g_csrc[min(e0 + grp, e1 - 1)]);
        uint4 r0 = __ldg(&XNH4[(size_t)u * 16 + sub * 2]);
        uint4 r1 = __ldg(&XNH4[(size_t)u * 16 + sub * 2 + 1]);

        for (int it = 0; it < niter; it++) {
            // ---- prefetch it+1 (overlaps compute below) ----
            int un = __ldg(&g_csrc[min(e0 + (it + 1) * 4 + grp, e1 - 1)]);
            uint4 n0 = __ldg(&XNH4[(size_t)un * 16 + sub * 2]);
            uint4 n1 = __ldg(&XNH4[(size_t)un * 16 + sub * 2 + 1]);

            bool valid = (e0 + it * 4 + grp) < e1;

            // ---- decode current into packed f32x2 ----
            unsigned long long f2[8];
            {
                const __half2* hp = (const __half2*)&r0;
#pragma unroll
                for (int q = 0; q < 4; q++) {
                    float2 t = __half22float2(hp[q]);
                    f2[q] = pack2(t.x, t.y);
                }
                const __half2* hq = (const __half2*)&r1;
#pragma unroll
                for (int q = 0; q < 4; q++) {
                    float2 t = __half22float2(hq[q]);
                    f2[4 + q] = pack2(t.x, t.y);
                }
            }

            // packed dot -> channel logit
            unsigned long long dp = 0ull;
#pragma unroll
            for (int j = 0; j < 8; j++) dp = ffma2(f2[j], sv[j], dp);
            float2 d2 = unpack2(dp);
            float pd = d2.x + d2.y;
            pd += __shfl_xor_sync(full, pd, 1);    // full channel logit (×log2e)
            float ev = ex2(pd);                     // own channel's exp
            float s2 = ev + __shfl_xor_sync(full, ev, 2);
            float denom = s2 + __shfl_xor_sync(full, s2, 4);
            float wgt = valid ? __fdividef(ev, denom) : 0.f;
            unsigned long long w2 = pack2(wgt, wgt);
#pragma unroll
            for (int j = 0; j < 8; j++) acc2[j] = ffma2(w2, f2[j], acc2[j]);

            r0 = n0; r1 = n1;
        }
    }

    // unpack + merge the 4 edge-group accumulators
    float acc[16];
#pragma unroll
    for (int j = 0; j < 8; j++) {
        float2 t = unpack2(acc2[j]);
        acc[2 * j] = t.x; acc[2 * j + 1] = t.y;
    }
#pragma unroll
    for (int j = 0; j < 16; j++) {
        acc[j] += __shfl_xor_sync(full, acc[j], 8);
        acc[j] += __shfl_xor_sync(full, acc[j], 16);
    }

    if (grp == 0) {
        if (MODE == 2) {
            float4* o = (float4*)(g_X + (size_t)v * DIM + sub * 16);
#pragma unroll
            for (int q = 0; q < 4; q++)
                o[q] = make_float4(acc[4 * q], acc[4 * q + 1], acc[4 * q + 2], acc[4 * q + 3]);
        } else {
            float ss = 0.f;
#pragma unroll
            for (int j = 0; j < 16; j++) ss = fmaf(acc[j], acc[j], ss);
            ss += __shfl_xor_sync(0xffu, ss, 1);   // other half of this channel
            float inv = 1.0f / fmaxf(sqrtf(ss), 1e-12f);
#pragma unroll
            for (int j = 0; j < 16; j++) acc[j] *= inv;
            float4 sout;
            sout.x = acc[0] + acc[1] + acc[2] + acc[3];
            sout.y = acc[4] + acc[5] + acc[6] + acc[7];
            sout.z = acc[8] + acc[9] + acc[10] + acc[11];
            sout.w = acc[12] + acc[13] + acc[14] + acc[15];
            ((float4*)(g_S + (size_t)v * 32))[sub] = sout;
            if (MODE == 1) {
                // layer boundary: publish normalized features.
                // fp16 goes to the OTHER buffer (B) — layer 1 gathers keep
                // reading buffer A untouched, so no cross-warp race.
                float4* xo = (float4*)(g_XN + (size_t)v * DIM + sub * 16);
                uint2* ho = g_XNHB + (size_t)v * 32 + sub * 4;
#pragma unroll
                for (int q = 0; q < 4; q++) {
                    xo[q] = make_float4(acc[4 * q], acc[4 * q + 1], acc[4 * q + 2], acc[4 * q + 3]);
                    __half2 h0 = __floats2half2_rn(acc[4 * q], acc[4 * q + 1]);
                    __half2 h1 = __floats2half2_rn(acc[4 * q + 2], acc[4 * q + 3]);
                    uint2 pk;
                    pk.x = *reinterpret_cast<unsigned int*>(&h0);
                    pk.y = *reinterpret_cast<unsigned int*>(&h1);
                    ho[q] = pk;
                }
            }
        }
    }
}

// ------------------------- launch -------------------------------------------
extern "C" void kernel_launch(void* const* d_in, const int* in_sizes, int n_in,
                              void* d_out, int out_size) {
    const float* feat  = (const float*)d_in[0];
    const void*  ei    = d_in[1];
    const float* lin_w = (const float*)d_in[2];
    const float* lin_b = (const float*)d_in[3];
    const float* mlp_w = (const float*)d_in[4];
    const float* mlp_b = (const float*)d_in[5];
    float* out = (float*)d_out;

    const int smem = (DIM * DIM + 64 * DIM) * (int)sizeof(float);  // 98304
    cudaFuncSetAttribute(k_gemm_in,  cudaFuncAttributeMaxDynamicSharedMemorySize, smem);
    cudaFuncSetAttribute(k_gemm_out, cudaFuncAttributeMaxDynamicSharedMemorySize, smem);

    // 1: detect edge_index dtype (int32 vs int64)
    k_detect<<<1, 128>>>((const int*)ei);
    // 2-3: CSR histogram
    k_zero<<<(NNODES + 255) / 256, 256>>>();
    k_hist<<<(MEDGE + 255) / 256, 256>>>(ei);
    // 4: x = feat @ lin_w + lin_b, fused channel-norm -> XN/XNHA/S
    k_gemm_in<<<(NNODES + 63) / 64, 256, smem>>>(feat, lin_w, lin_b);
    // 5-7: finish CSR
    k_scan1<<<SCAN_NB, SCAN_BS>>>();
    k_scan3<<<(NNODES + 255) / 256, 256>>>();
    k_fill<<<(MEDGE + 255) / 256, 256>>>(ei);

    // layer 1: gather from buffer A; boundary norm writes buffer B
    k_edge<0, 0><<<NODE_BLKS, NWARPBLK * 32>>>();
    k_edge<0, 0><<<NODE_BLKS, NWARPBLK * 32>>>();
    k_edge<1, 0><<<NODE_BLKS, NWARPBLK * 32>>>();
    // layer 2: gather from buffer B; final raw output -> g_X
    k_edge<0, 1><<<NODE_BLKS, NWARPBLK * 32>>>();
    k_edge<0, 1><<<NODE_BLKS, NWARPBLK * 32>>>();
    k_edge<2, 1><<<NODE_BLKS, NWARPBLK * 32>>>();

    // out = x @ mlp_w + mlp_b ; epilogue streams x into out[NNODES*DIM..]
    k_gemm_out<<<(NNODES + 63) / 64, 256, smem>>>(mlp_w, mlp_b, out,
                                                  out + (size_t)NNODES * DIM);
}

// round 13
// speedup vs baseline: 1.2628x; 1.2628x over previous
#include <cuda_runtime.h>
#include <cuda_fp16.h>
#include <math.h>

#define NNODES 50000
#define DIM 128
#define MEDGE 800000
#define NWARPBLK 8
#define NODE_BLKS ((NNODES + NWARPBLK - 1) / NWARPBLK)   // 6250
#define SCAN_BS 1024
#define SCAN_NB ((NNODES + SCAN_BS - 1) / SCAN_BS)        // 49
#define CAP 32                                            // cached edges per node
#define ROUTIT 3

// ------------------------- scratch (static device memory) -------------------
__device__ float g_X[NNODES * DIM];     // raw routing output (layer 2 only)
__device__ float g_XN[NNODES * DIM];    // normalized x, fp32 (self term)
__device__ uint2 g_XNHA[NNODES * 32];   // normalized x fp16, layer-1 gathers
__device__ uint2 g_XNHB[NNODES * 32];   // normalized x fp16, layer-2 gathers
__device__ float g_S[NNODES * 32];      // per-node s vector
__device__ int   g_deg[NNODES];
__device__ int   g_tmp[NNODES];
__device__ int   g_rowoff[NNODES + 1];
__device__ int   g_cursor[NNODES + 1];
__device__ int   g_csrc[MEDGE];
__device__ int   g_bsum[64];
__device__ int   g_is64;

__device__ __forceinline__ float ex2(float x) {
    float r;
    asm("ex2.approx.f32 %0, %1;" : "=f"(r) : "f"(x));
    return r;
}

// ------------------------- edge index dtype handling ------------------------
__global__ void k_detect(const int* __restrict__ ei) {
    __shared__ int nz;
    if (threadIdx.x == 0) nz = 0;
    __syncthreads();
    if (ei[2 * threadIdx.x + 1] != 0) atomicOr(&nz, 1);
    __syncthreads();
    if (threadIdx.x == 0) g_is64 = nz ? 0 : 1;
}

__device__ __forceinline__ int load_idx(const void* ei, long long pos, int is64) {
    if (is64) return (int)((const long long*)ei)[pos];
    return ((const int*)ei)[pos];
}

// ------------------------- CSR build ----------------------------------------
__global__ void k_zero() {
    int i = blockIdx.x * blockDim.x + threadIdx.x;
    if (i < NNODES) g_deg[i] = 0;
}

__global__ void k_hist(const void* __restrict__ ei) {
    int e = blockIdx.x * blockDim.x + threadIdx.x;
    if (e < MEDGE) {
        int t = load_idx(ei, (long long)MEDGE + e, g_is64);
        atomicAdd(&g_deg[t], 1);
    }
}

__global__ void k_scan1() {
    __shared__ int wsum[32];
    const unsigned full = 0xffffffffu;
    int i = blockIdx.x * SCAN_BS + threadIdx.x;
    int lane = threadIdx.x & 31;
    int wid = threadIdx.x >> 5;
    int s = (i < NNODES) ? g_deg[i] : 0;
#pragma unroll
    for (int o = 1; o < 32; o <<= 1) {
        int t = __shfl_up_sync(full, s, o);
        if (lane >= o) s += t;
    }
    if (lane == 31) wsum[wid] = s;
    __syncthreads();
    if (wid == 0) {
        int w = wsum[lane];
#pragma unroll
        for (int o = 1; o < 32; o <<= 1) {
            int t = __shfl_up_sync(full, w, o);
            if (lane >= o) w += t;
        }
        wsum[lane] = w;
    }
    __syncthreads();
    int total = s + (wid ? wsum[wid - 1] : 0);
    if (i < NNODES) g_tmp[i] = total;
    if (threadIdx.x == SCAN_BS - 1) g_bsum[blockIdx.x] = total;
}

__global__ void k_scan3() {
    __shared__ int bx[SCAN_NB];
    if (threadIdx.x < SCAN_NB) bx[threadIdx.x] = g_bsum[threadIdx.x];
    __syncthreads();
    if (threadIdx.x == 0) {
        int run = 0;
#pragma unroll
        for (int b = 0; b < SCAN_NB; b++) { int t = bx[b]; bx[b] = run; run += t; }
    }
    __syncthreads();
    int i = blockIdx.x * blockDim.x + threadIdx.x;
    if (i < NNODES) {
        int inc = g_tmp[i] + bx[i >> 10];
        g_rowoff[i + 1] = inc;
        g_cursor[i + 1] = inc;
        if (i == 0) { g_rowoff[0] = 0; g_cursor[0] = 0; }
    }
}

__global__ void k_fill(const void* __restrict__ ei) {
    int e = blockIdx.x * blockDim.x + threadIdx.x;
    if (e < MEDGE) {
        int is64 = g_is64;
        int t = load_idx(ei, (long long)MEDGE + e, is64);
        int s = load_idx(ei, e, is64);
        int pos = atomicAdd(&g_cursor[t], 1);
        g_csrc[pos] = s;
    }
}

// ------------------------- GEMM (rows x 128) @ (128 x 128) + bias -----------
template <bool NORM_EPI, bool COPY_A>
__device__ __forceinline__ void gemm_body(const float* __restrict__ A,
                                          const float* __restrict__ W,
                                          const float* __restrict__ bias,
                                          float* __restrict__ C,
                                          float* __restrict__ Acopy, int nrows) {
    extern __shared__ float sh[];
    float4* Ws4 = (float4*)sh;                 // 128x128 floats
    float4* As4 = (float4*)(sh + DIM * DIM);   // 64x128 floats
    int tid = threadIdx.x;            // 256 threads
    int tx = tid & 31;                // column group (4 cols)
    int ty = tid >> 5;                // row group (8 rows) == warp id
    int row0 = blockIdx.x * 64;
    const unsigned full = 0xffffffffu;

    const float4* W4 = (const float4*)W;
#pragma unroll
    for (int i = 0; i < 16; i++) Ws4[tid + i * 256] = W4[tid + i * 256];
#pragma unroll
    for (int i = 0; i < 8; i++) {
        int idx = tid + i * 256;
        int r = idx >> 5;
        float4 v = make_float4(0.f, 0.f, 0.f, 0.f);
        if (row0 + r < nrows) v = ((const float4*)A)[(size_t)(row0 + r) * 32 + (idx & 31)];
        As4[idx] = v;
    }
    __syncthreads();

    float4 acc[8];
#pragma unroll
    for (int r = 0; r < 8; r++) acc[r] = make_float4(0.f, 0.f, 0.f, 0.f);

#pragma unroll
    for (int k4 = 0; k4 < 32; k4++) {
        float4 w0 = Ws4[(k4 * 4 + 0) * 32 + tx];
        float4 w1 = Ws4[(k4 * 4 + 1) * 32 + tx];
        float4 w2 = Ws4[(k4 * 4 + 2) * 32 + tx];
        float4 w3 = Ws4[(k4 * 4 + 3) * 32 + tx];
#pragma unroll
        for (int r = 0; r < 8; r++) {
            float4 a = As4[(ty * 8 + r) * 32 + k4];
            acc[r].x = fmaf(a.x, w0.x, fmaf(a.y, w1.x, fmaf(a.z, w2.x, fmaf(a.w, w3.x, acc[r].x))));
            acc[r].y = fmaf(a.x, w0.y, fmaf(a.y, w1.y, fmaf(a.z, w2.y, fmaf(a.w, w3.y, acc[r].y))));
            acc[r].z = fmaf(a.x, w0.z, fmaf(a.y, w1.z, fmaf(a.z, w2.z, fmaf(a.w, w3.z, acc[r].z))));
            acc[r].w = fmaf(a.x, w0.w, fmaf(a.y, w1.w, fmaf(a.z, w2.w, fmaf(a.w, w3.w, acc[r].w))));
        }
    }

    float4 b4 = ((const float4*)bias)[tx];
#pragma unroll
    for (int r = 0; r < 8; r++) {
        int row = row0 + ty * 8 + r;
        float4 o = acc[r];
        o.x += b4.x; o.y += b4.y; o.z += b4.z; o.w += b4.w;
        if (NORM_EPI) {
            float ss = o.x * o.x + o.y * o.y + o.z * o.z + o.w * o.w;
            ss += __shfl_xor_sync(full, ss, 1);
            ss += __shfl_xor_sync(full, ss, 2);
            ss += __shfl_xor_sync(full, ss, 4);
            float inv = 1.0f / fmaxf(sqrtf(ss), 1e-12f);
            o.x *= inv; o.y *= inv; o.z *= inv; o.w *= inv;
            if (row < nrows) {
                ((float4*)g_XN)[(size_t)row * 32 + tx] = o;
                __half2 h0 = __floats2half2_rn(o.x, o.y);
                __half2 h1 = __floats2half2_rn(o.z, o.w);
                uint2 pk;
                pk.x = *reinterpret_cast<unsigned int*>(&h0);
                pk.y = *reinterpret_cast<unsigned int*>(&h1);
                g_XNHA[(size_t)row * 32 + tx] = pk;
                g_S[(size_t)row * 32 + tx] = o.x + o.y + o.z + o.w;
            }
        } else {
            if (row < nrows) ((float4*)C)[(size_t)row * 32 + tx] = o;
        }
    }

    if (COPY_A) {
#pragma unroll
        for (int i = 0; i < 8; i++) {
            int idx = tid + i * 256;
            int r = idx >> 5;
            if (row0 + r < nrows)
                ((float4*)Acopy)[(size_t)(row0 + r) * 32 + (idx & 31)] = As4[idx];
        }
    }
}

__global__ void k_gemm_in(const float* __restrict__ A, const float* __restrict__ W,
                          const float* __restrict__ b) {
    gemm_body<true, false>(A, W, b, nullptr, nullptr, NNODES);
}

__global__ void k_gemm_out(const float* __restrict__ W, const float* __restrict__ b,
                           float* __restrict__ C, float* __restrict__ Xout) {
    gemm_body<false, true>(g_X, W, b, C, Xout, NNODES);
}

// ------------------------- whole layer: 3 routing iterations ---------------
// One warp per target node. Neighbor fp16 rows cached in smem (CAP edges);
// all 3 routing iterations run in-kernel (no cross-node dependency within a
// layer: s uses only the target's own vector; z = xn[src] is layer-constant).
// MODE 1: final iteration writes XN (fp32) + XNHB (fp16) + S  (layer boundary)
// MODE 2: final iteration writes raw c to g_X                 (last layer)
__device__ __forceinline__ void decode16(uint4 r0, uint4 r1, float* f) {
    const __half2* hp = (const __half2*)&r0;
#pragma unroll
    for (int q = 0; q < 4; q++) {
        float2 t = __half22float2(hp[q]);
        f[2 * q] = t.x; f[2 * q + 1] = t.y;
    }
    const __half2* hq = (const __half2*)&r1;
#pragma unroll
    for (int q = 0; q < 4; q++) {
        float2 t = __half22float2(hq[q]);
        f[8 + 2 * q] = t.x; f[8 + 2 * q + 1] = t.y;
    }
}

template <int MODE, int BUF>
__global__ void __launch_bounds__(NWARPBLK * 32) k_layer() {
    extern __shared__ uint4 smz[];
    // layout: [NWARPBLK][CAP*16] uint4 z-cache, then [NWARPBLK][32] float sbuf
    int wwarp = threadIdx.x >> 5;
    int v = blockIdx.x * NWARPBLK + wwarp;
    int lane = threadIdx.x & 31;
    if (v >= NNODES) return;
    int grp = lane >> 3;          // edge slot 0..3
    int sub = lane & 7;           // lane within edge group
    int half = sub & 1;           // which 16-element half of the channel
    const unsigned full = 0xffffffffu;
    const float LOG2E = 1.4426950408889634f;

    uint4* zc = smz + (size_t)wwarp * (CAP * 16);
    float* sbuf = ((float*)(smz + NWARPBLK * CAP * 16)) + wwarp * 32;

    int e0 = g_rowoff[v];
    int e1 = g_rowoff[v + 1];
    int nE = e1 - e0;
    int cached = nE < CAP ? nE : CAP;
    int niter = (nE + 3) >> 2;
    const uint4* XNH4 = (const uint4*)(BUF == 0 ? g_XNHA : g_XNHB);

    // ---- gather phase: fill smem z-cache (once per layer) ----
    for (int idx = grp; idx < cached; idx += 4) {
        int u = __ldg(&g_csrc[e0 + idx]);
        uint4 a = __ldg(&XNH4[(size_t)u * 16 + sub * 2]);
        uint4 b = __ldg(&XNH4[(size_t)u * 16 + sub * 2 + 1]);
        zc[idx * 16 + sub * 2] = a;
        zc[idx * 16 + sub * 2 + 1] = b;
    }
    __syncwarp();

    // initial sv from g_S (pre-scaled by log2 e; TAU = 1)
    float sv[16];
    {
        const float4* srow = (const float4*)(g_S + (size_t)v * 32 + half * 16);
#pragma unroll
        for (int q = 0; q < 4; q++) {
            float4 t = srow[q];
            sv[4 * q + 0] = t.x * LOG2E;
            sv[4 * q + 1] = t.y * LOG2E;
            sv[4 * q + 2] = t.z * LOG2E;
            sv[4 * q + 3] = t.w * LOG2E;
        }
    }

    const float4* xnrow = (const float4*)(g_XN + (size_t)v * DIM + sub * 16);

    for (int t = 0; t < ROUTIT; t++) {
        // seed accumulator: group 0 carries the self term x_norm[v]
        float acc[16];
        if (grp == 0) {
#pragma unroll
            for (int q = 0; q < 4; q++) {
                float4 tt = xnrow[q];
                acc[4 * q + 0] = tt.x; acc[4 * q + 1] = tt.y;
                acc[4 * q + 2] = tt.z; acc[4 * q + 3] = tt.w;
            }
        } else {
#pragma unroll
            for (int j = 0; j < 16; j++) acc[j] = 0.f;
        }

        for (int it = 0; it < niter; it++) {
            int idx = it * 4 + grp;
            bool valid = idx < nE;
            float f[16];
            if (idx < cached) {
                uint4 r0 = zc[idx * 16 + sub * 2];
                uint4 r1 = zc[idx * 16 + sub * 2 + 1];
                decode16(r0, r1, f);
            } else if (valid) {
                int u = __ldg(&g_csrc[e0 + idx]);
                uint4 r0 = __ldg(&XNH4[(size_t)u * 16 + sub * 2]);
                uint4 r1 = __ldg(&XNH4[(size_t)u * 16 + sub * 2 + 1]);
                decode16(r0, r1, f);
            } else {
#pragma unroll
                for (int j = 0; j < 16; j++) f[j] = 0.f;
            }

            float pd = 0.f;
#pragma unroll
            for (int j = 0; j < 16; j++) pd = fmaf(f[j], sv[j], pd);
            pd += __shfl_xor_sync(full, pd, 1);   // full channel logit (×log2e)
            float ev = ex2(pd);                    // own channel's exp
            float s2 = ev + __shfl_xor_sync(full, ev, 2);
            float denom = s2 + __shfl_xor_sync(full, s2, 4);
            float wgt = valid ? __fdividef(ev, denom) : 0.f;
#pragma unroll
            for (int j = 0; j < 16; j++) acc[j] = fmaf(wgt, f[j], acc[j]);
        }

        // merge the 4 edge-group accumulators (all lanes end with full sums)
#pragma unroll
        for (int j = 0; j < 16; j++) {
            acc[j] += __shfl_xor_sync(full, acc[j], 8);
            acc[j] += __shfl_xor_sync(full, acc[j], 16);
        }

        if (t < ROUTIT - 1) {
            // channel-normalize, rebuild s, exchange via per-warp smem buffer
            float ss = 0.f;
#pragma unroll
            for (int j = 0; j < 16; j++) ss = fmaf(acc[j], acc[j], ss);
            ss += __shfl_xor_sync(full, ss, 1);    // other half of this channel
            float inv = 1.0f / fmaxf(sqrtf(ss), 1e-12f);
            if (grp == 0) {
                float4 qs;
                qs.x = (acc[0] + acc[1] + acc[2] + acc[3]) * inv;
                qs.y = (acc[4] + acc[5] + acc[6] + acc[7]) * inv;
                qs.z = (acc[8] + acc[9] + acc[10] + acc[11]) * inv;
                qs.w = (acc[12] + acc[13] + acc[14] + acc[15]) * inv;
                ((float4*)sbuf)[sub] = qs;          // s[4*sub .. 4*sub+3]
            }
            __syncwarp();
            const float4* srow = (const float4*)(sbuf + half * 16);
#pragma unroll
            for (int q = 0; q < 4; q++) {
                float4 tt = srow[q];
                sv[4 * q + 0] = tt.x * LOG2E;
                sv[4 * q + 1] = tt.y * LOG2E;
                sv[4 * q + 2] = tt.z * LOG2E;
                sv[4 * q + 3] = tt.w * LOG2E;
            }
            __syncwarp();
        } else if (grp == 0) {
            if (MODE == 2) {
                float4* o = (float4*)(g_X + (size_t)v * DIM + sub * 16);
#pragma unroll
                for (int q = 0; q < 4; q++)
                    o[q] = make_float4(acc[4 * q], acc[4 * q + 1],
                                       acc[4 * q + 2], acc[4 * q + 3]);
            } else {
                // layer boundary: normalize and publish XN / XNHB / S
                float ss = 0.f;
#pragma unroll
                for (int j = 0; j < 16; j++) ss = fmaf(acc[j], acc[j], ss);
                ss += __shfl_xor_sync(0xffu, ss, 1);
                float inv = 1.0f / fmaxf(sqrtf(ss), 1e-12f);
#pragma unroll
                for (int j = 0; j < 16; j++) acc[j] *= inv;
                float4 sout;
                sout.x = acc[0] + acc[1] + acc[2] + acc[3];
                sout.y = acc[4] + acc[5] + acc[6] + acc[7];
                sout.z = acc[8] + acc[9] + acc[10] + acc[11];
                sout.w = acc[12] + acc[13] + acc[14] + acc[15];
                ((float4*)(g_S + (size_t)v * 32))[sub] = sout;
                float4* xo = (float4*)(g_XN + (size_t)v * DIM + sub * 16);
                uint2* ho = g_XNHB + (size_t)v * 32 + sub * 4;
#pragma unroll
                for (int q = 0; q < 4; q++) {
                    xo[q] = make_float4(acc[4 * q], acc[4 * q + 1],
                                        acc[4 * q + 2], acc[4 * q + 3]);
                    __half2 h0 = __floats2half2_rn(acc[4 * q], acc[4 * q + 1]);
                    __half2 h1 = __floats2half2_rn(acc[4 * q + 2], acc[4 * q + 3]);
                    uint2 pk;
                    pk.x = *reinterpret_cast<unsigned int*>(&h0);
                    pk.y = *reinterpret_cast<unsigned int*>(&h1);
                    ho[q] = pk;
                }
            }
        }
    }
}

// ------------------------- launch -------------------------------------------
extern "C" void kernel_launch(void* const* d_in, const int* in_sizes, int n_in,
                              void* d_out, int out_size) {
    const float* feat  = (const float*)d_in[0];
    const void*  ei    = d_in[1];
    const float* lin_w = (const float*)d_in[2];
    const float* lin_b = (const float*)d_in[3];
    const float* mlp_w = (const float*)d_in[4];
    const float* mlp_b = (const float*)d_in[5];
    float* out = (float*)d_out;

    const int smem = (DIM * DIM + 64 * DIM) * (int)sizeof(float);     // 98304
    const int lsmem = NWARPBLK * CAP * 16 * 16 + NWARPBLK * 32 * 4;   // 66560
    cudaFuncSetAttribute(k_gemm_in,  cudaFuncAttributeMaxDynamicSharedMemorySize, smem);
    cudaFuncSetAttribute(k_gemm_out, cudaFuncAttributeMaxDynamicSharedMemorySize, smem);
    cudaFuncSetAttribute(k_layer<1, 0>, cudaFuncAttributeMaxDynamicSharedMemorySize, lsmem);
    cudaFuncSetAttribute(k_layer<2, 1>, cudaFuncAttributeMaxDynamicSharedMemorySize, lsmem);

    // 1: detect edge_index dtype (int32 vs int64)
    k_detect<<<1, 128>>>((const int*)ei);
    // 2-3: CSR histogram
    k_zero<<<(NNODES + 255) / 256, 256>>>();
    k_hist<<<(MEDGE + 255) / 256, 256>>>(ei);
    // 4: x = feat @ lin_w + lin_b, fused channel-norm -> XN/XNHA/S
    k_gemm_in<<<(NNODES + 63) / 64, 256, smem>>>(feat, lin_w, lin_b);
    // 5-7: finish CSR
    k_scan1<<<SCAN_NB, SCAN_BS>>>();
    k_scan3<<<(NNODES + 255) / 256, 256>>>();
    k_fill<<<(MEDGE + 255) / 256, 256>>>(ei);

    // 8: layer 1 (all 3 routing iterations; gathers A, publishes B)
    k_layer<1, 0><<<NODE_BLKS, NWARPBLK * 32, lsmem>>>();
    // 9: layer 2 (gathers B, writes raw c -> g_X)
    k_layer<2, 1><<<NODE_BLKS, NWARPBLK * 32, lsmem>>>();

    // 10: out = x @ mlp_w + mlp_b ; epilogue streams x into out[NNODES*DIM..]
    k_gemm_out<<<(NNODES + 63) / 64, 256, smem>>>(mlp_w, mlp_b, out,
                                                  out + (size_t)NNODES * DIM);
}

// round 14
// speedup vs baseline: 1.3576x; 1.0751x over previous
#include <cuda_runtime.h>
#include <cuda_fp16.h>
#include <math.h>

#define NNODES 50000
#define DIM 128
#define MEDGE 800000
#define NWARPBLK 8
#define NODE_BLKS ((NNODES + NWARPBLK - 1) / NWARPBLK)   // 6250
#define SCAN_BS 1024
#define SCAN_NB ((NNODES + SCAN_BS - 1) / SCAN_BS)        // 49
#define CAP 32                                            // cached edges per node
#define ROUTIT 3

// tensor GEMM tiling
#define TG_ROWS 64
#define TG_THREADS 128
#define TG_STRIDE 136        // halves per smem row (128 + 8 pad)
#define TG_BLOCKS ((NNODES + TG_ROWS - 1) / TG_ROWS)      // 782
// smem half-offsets
#define OFF_AL (TG_ROWS * TG_STRIDE)                      // 8704
#define OFF_WH (2 * TG_ROWS * TG_STRIDE)                  // 17408
#define OFF_WL (OFF_WH + DIM * TG_STRIDE)                 // 34816
#define TG_SMEM ((OFF_WL + DIM * TG_STRIDE) * 2)          // 104448 bytes

// ------------------------- scratch (static device memory) -------------------
__device__ float g_X[NNODES * DIM];     // raw routing output (layer 2 only)
__device__ float g_XN[NNODES * DIM];    // normalized x, fp32 (self term)
__device__ uint2 g_XNHA[NNODES * 32];   // normalized x fp16, layer-1 gathers
__device__ uint2 g_XNHB[NNODES * 32];   // normalized x fp16, layer-2 gathers
__device__ float g_S[NNODES * 32];      // per-node s vector
__device__ int   g_deg[NNODES];
__device__ int   g_tmp[NNODES];
__device__ int   g_rowoff[NNODES + 1];
__device__ int   g_cursor[NNODES + 1];
__device__ int   g_csrc[MEDGE];
__device__ int   g_bsum[64];
__device__ int   g_is64;

__device__ __forceinline__ float ex2(float x) {
    float r;
    asm("ex2.approx.f32 %0, %1;" : "=f"(r) : "f"(x));
    return r;
}

__device__ __forceinline__ unsigned smem_u32(const void* p) {
    unsigned a;
    asm("{ .reg .u64 t; cvta.to.shared.u64 t, %1; cvt.u32.u64 %0, t; }"
        : "=r"(a) : "l"(p));
    return a;
}

__device__ __forceinline__ void ldmx4(unsigned* r, unsigned addr) {
    asm volatile("ldmatrix.sync.aligned.m8n8.x4.shared.b16 {%0,%1,%2,%3}, [%4];"
                 : "=r"(r[0]), "=r"(r[1]), "=r"(r[2]), "=r"(r[3]) : "r"(addr));
}
__device__ __forceinline__ void ldmx2t(unsigned* r, unsigned addr) {
    asm volatile("ldmatrix.sync.aligned.m8n8.x2.trans.shared.b16 {%0,%1}, [%2];"
                 : "=r"(r[0]), "=r"(r[1]) : "r"(addr));
}
__device__ __forceinline__ void mma16816(float* c, const unsigned* a, const unsigned* b) {
    asm volatile("mma.sync.aligned.m16n8k16.row.col.f32.f16.f16.f32 "
                 "{%0,%1,%2,%3}, {%4,%5,%6,%7}, {%8,%9}, {%0,%1,%2,%3};"
                 : "+f"(c[0]), "+f"(c[1]), "+f"(c[2]), "+f"(c[3])
                 : "r"(a[0]), "r"(a[1]), "r"(a[2]), "r"(a[3]), "r"(b[0]), "r"(b[1]));
}

// split a float pair into fp16 hi + fp16 residue
__device__ __forceinline__ void split2(float x, float y, __half2& h, __half2& l) {
    h = __floats2half2_rn(x, y);
    float2 hf = __half22float2(h);
    l = __floats2half2_rn(x - hf.x, y - hf.y);
}

// ------------------------- edge index dtype handling ------------------------
__global__ void k_detect(const int* __restrict__ ei) {
    __shared__ int nz;
    if (threadIdx.x == 0) nz = 0;
    __syncthreads();
    if (ei[2 * threadIdx.x + 1] != 0) atomicOr(&nz, 1);
    __syncthreads();
    if (threadIdx.x == 0) g_is64 = nz ? 0 : 1;
}

__device__ __forceinline__ int load_idx(const void* ei, long long pos, int is64) {
    if (is64) return (int)((const long long*)ei)[pos];
    return ((const int*)ei)[pos];
}

// ------------------------- CSR build ----------------------------------------
__global__ void k_zero() {
    int i = blockIdx.x * blockDim.x + threadIdx.x;
    if (i < NNODES) g_deg[i] = 0;
}

__global__ void k_hist(const void* __restrict__ ei) {
    int e = blockIdx.x * blockDim.x + threadIdx.x;
    if (e < MEDGE) {
        int t = load_idx(ei, (long long)MEDGE + e, g_is64);
        atomicAdd(&g_deg[t], 1);
    }
}

__global__ void k_scan1() {
    __shared__ int wsum[32];
    const unsigned full = 0xffffffffu;
    int i = blockIdx.x * SCAN_BS + threadIdx.x;
    int lane = threadIdx.x & 31;
    int wid = threadIdx.x >> 5;
    int s = (i < NNODES) ? g_deg[i] : 0;
#pragma unroll
    for (int o = 1; o < 32; o <<= 1) {
        int t = __shfl_up_sync(full, s, o);
        if (lane >= o) s += t;
    }
    if (lane == 31) wsum[wid] = s;
    __syncthreads();
    if (wid == 0) {
        int w = wsum[lane];
#pragma unroll
        for (int o = 1; o < 32; o <<= 1) {
            int t = __shfl_up_sync(full, w, o);
            if (lane >= o) w += t;
        }
        wsum[lane] = w;
    }
    __syncthreads();
    int total = s + (wid ? wsum[wid - 1] : 0);
    if (i < NNODES) g_tmp[i] = total;
    if (threadIdx.x == SCAN_BS - 1) g_bsum[blockIdx.x] = total;
}

__global__ void k_scan3() {
    __shared__ int bx[SCAN_NB];
    if (threadIdx.x < SCAN_NB) bx[threadIdx.x] = g_bsum[threadIdx.x];
    __syncthreads();
    if (threadIdx.x == 0) {
        int run = 0;
#pragma unroll
        for (int b = 0; b < SCAN_NB; b++) { int t = bx[b]; bx[b] = run; run += t; }
    }
    __syncthreads();
    int i = blockIdx.x * blockDim.x + threadIdx.x;
    if (i < NNODES) {
        int inc = g_tmp[i] + bx[i >> 10];
        g_rowoff[i + 1] = inc;
        g_cursor[i + 1] = inc;
        if (i == 0) { g_rowoff[0] = 0; g_cursor[0] = 0; }
    }
}

__global__ void k_fill(const void* __restrict__ ei) {
    int e = blockIdx.x * blockDim.x + threadIdx.x;
    if (e < MEDGE) {
        int is64 = g_is64;
        int t = load_idx(ei, (long long)MEDGE + e, is64);
        int s = load_idx(ei, e, is64);
        int pos = atomicAdd(&g_cursor[t], 1);
        g_csrc[pos] = s;
    }
}

// --------------- tensor-core GEMM (rows x 128) @ (128 x 128) + bias ---------
// Split-fp16: X = Xh + Xl per operand; D = Ah*Wh + Ah*Wl + Al*Wh (fp32 acc).
// NORM_EPI: channel-normalize each output row, write XN/XNHA/S.
// COPY_A:  stream the fp32 A rows to Acopy during load.
template <bool NORM_EPI, bool COPY_A>
__device__ __forceinline__ void tgemm_body(const float* __restrict__ A,
                                           const float* __restrict__ W,
                                           const float* __restrict__ bias,
                                           float* __restrict__ C,
                                           float* __restrict__ Acopy, int nrows) {
    extern __shared__ __half smh[];
    const int tid = threadIdx.x;
    const int row0 = blockIdx.x * TG_ROWS;
    const unsigned full = 0xffffffffu;

    // ---- load W (128x128) as hi/lo fp16 splits ----
    const float4* W4 = (const float4*)W;
#pragma unroll
    for (int i = 0; i < 32; i++) {
        int idx = tid + i * TG_THREADS;
        int r = idx >> 5, c = idx & 31;
        float4 w = W4[r * 32 + c];
        __half2 h0, l0, h1, l1;
        split2(w.x, w.y, h0, l0);
        split2(w.z, w.w, h1, l1);
        int off = r * TG_STRIDE + c * 4;
        ((__half2*)(smh + OFF_WH + off))[0] = h0;
        ((__half2*)(smh + OFF_WH + off))[1] = h1;
        ((__half2*)(smh + OFF_WL + off))[0] = l0;
        ((__half2*)(smh + OFF_WL + off))[1] = l1;
    }
    // ---- load A tile (64x128) ----
    const float4* A4 = (const float4*)A;
#pragma unroll
    for (int i = 0; i < 16; i++) {
        int idx = tid + i * TG_THREADS;
        int r = idx >> 5, c = idx & 31;
        float4 a = make_float4(0.f, 0.f, 0.f, 0.f);
        if (row0 + r < nrows) {
            a = A4[(size_t)(row0 + r) * 32 + c];
            if (COPY_A) ((float4*)Acopy)[(size_t)(row0 + r) * 32 + c] = a;
        }
        __half2 h0, l0, h1, l1;
        split2(a.x, a.y, h0, l0);
        split2(a.z, a.w, h1, l1);
        int off = r * TG_STRIDE + c * 4;
        ((__half2*)(smh + off))[0] = h0;
        ((__half2*)(smh + off))[1] = h1;
        ((__half2*)(smh + OFF_AL + off))[0] = l0;
        ((__half2*)(smh + OFF_AL + off))[1] = l1;
    }
    __syncthreads();

    const int lane = tid & 31;
    const int warp = tid >> 5;
    const int m0 = warp * 16;

    unsigned sb = smem_u32(smh);
    unsigned aoff = (unsigned)((m0 + (lane & 15)) * TG_STRIDE + (lane >> 4) * 8) * 2;
    unsigned a_h = sb + aoff;
    unsigned a_l = sb + OFF_AL * 2 + aoff;
    unsigned brow = (unsigned)((lane & 15) * TG_STRIDE) * 2;
    unsigned b_h0 = sb + OFF_WH * 2 + brow;
    unsigned b_l0 = sb + OFF_WL * 2 + brow;

    float acc[16][4];
#pragma unroll
    for (int t = 0; t < 16; t++)
#pragma unroll
        for (int j = 0; j < 4; j++) acc[t][j] = 0.f;

#pragma unroll
    for (int k = 0; k < 8; k++) {
        unsigned ah[4], al[4];
        ldmx4(ah, a_h + k * 32);
        ldmx4(al, a_l + k * 32);
        unsigned bk = (unsigned)(k * 16 * TG_STRIDE) * 2;
#pragma unroll
        for (int t = 0; t < 16; t++) {
            unsigned bh[2], bl[2];
            ldmx2t(bh, b_h0 + bk + t * 16);
            ldmx2t(bl, b_l0 + bk + t * 16);
            mma16816(acc[t], ah, bh);
            mma16816(acc[t], ah, bl);
            mma16816(acc[t], al, bh);
        }
    }

    // ---- epilogue ----
    const int qr = lane >> 2;      // 0..7
    const int qc = lane & 3;       // 0..3
    int r0g = row0 + m0 + qr;      // rows for acc[.][0..1]
    int r1g = r0g + 8;             // rows for acc[.][2..3]

#pragma unroll
    for (int t = 0; t < 16; t++) {
        float2 bb = __ldg((const float2*)(bias + t * 8 + qc * 2));
        acc[t][0] += bb.x; acc[t][1] += bb.y;
        acc[t][2] += bb.x; acc[t][3] += bb.y;
    }

    if (!NORM_EPI) {
#pragma unroll
        for (int t = 0; t < 16; t++) {
            if (r0g < nrows)
                *(float2*)(C + (size_t)r0g * DIM + t * 8 + qc * 2) =
                    make_float2(acc[t][0], acc[t][1]);
            if (r1g < nrows)
                *(float2*)(C + (size_t)r1g * DIM + t * 8 + qc * 2) =
                    make_float2(acc[t][2], acc[t][3]);
        }
    } else {
        // per-row, per-channel sum of squares (channel = tile>>2)
        float ss0[4] = {0.f, 0.f, 0.f, 0.f};
        float ss1[4] = {0.f, 0.f, 0.f, 0.f};
#pragma unroll
        for (int t = 0; t < 16; t++) {
            int ch = t >> 2;
            ss0[ch] = fmaf(acc[t][0], acc[t][0], fmaf(acc[t][1], acc[t][1], ss0[ch]));
            ss1[ch] = fmaf(acc[t][2], acc[t][2], fmaf(acc[t][3], acc[t][3], ss1[ch]));
        }
        float inv0[4], inv1[4];
#pragma unroll
        for (int ch = 0; ch < 4; ch++) {
            float s0 = ss0[ch];
            s0 += __shfl_xor_sync(full, s0, 1);
            s0 += __shfl_xor_sync(full, s0, 2);
            inv0[ch] = 1.0f / fmaxf(sqrtf(s0), 1e-12f);
            float s1 = ss1[ch];
            s1 += __shfl_xor_sync(full, s1, 1);
            s1 += __shfl_xor_sync(full, s1, 2);
            inv1[ch] = 1.0f / fmaxf(sqrtf(s1), 1e-12f);
        }
        unsigned* XNHu = (unsigned*)g_XNHA;
#pragma unroll
        for (int t = 0; t < 16; t++) {
            int ch = t >> 2;
            float x0 = acc[t][0] * inv0[ch], y0 = acc[t][1] * inv0[ch];
            float x1 = acc[t][2] * inv1[ch], y1 = acc[t][3] * inv1[ch];
            // S partials: pair (qc even) covers cols 4a..4a+3
            float s0 = x0 + y0, s1 = x1 + y1;
            float p0 = __shfl_xor_sync(full, s0, 1);
            float p1 = __shfl_xor_sync(full, s1, 1);
            if (r0g < nrows) {
                *(float2*)(g_XN + (size_t)r0g * DIM + t * 8 + qc * 2) = make_float2(x0, y0);
                __half2 hh = __floats2half2_rn(x0, y0);
                XNHu[(size_t)r0g * 64 + t * 4 + qc] = *(unsigned*)&hh;
                if ((qc & 1) == 0) g_S[(size_t)r0g * 32 + t * 2 + (qc >> 1)] = s0 + p0;
            }
            if (r1g < nrows) {
                *(float2*)(g_XN + (size_t)r1g * DIM + t * 8 + qc * 2) = make_float2(x1, y1);
                __half2 hh = __floats2half2_rn(x1, y1);
                XNHu[(size_t)r1g * 64 + t * 4 + qc] = *(unsigned*)&hh;
                if ((qc & 1) == 0) g_S[(size_t)r1g * 32 + t * 2 + (qc >> 1)] = s1 + p1;
            }
        }
    }
}

__global__ void __launch_bounds__(TG_THREADS) k_gemm_in(const float* __restrict__ A,
                                                        const float* __restrict__ W,
                                                        const float* __restrict__ b) {
    tgemm_body<true, false>(A, W, b, nullptr, nullptr, NNODES);
}

__global__ void __launch_bounds__(TG_THREADS) k_gemm_out(const float* __restrict__ W,
                                                         const float* __restrict__ b,
                                                         float* __restrict__ C,
                                                         float* __restrict__ Xout) {
    tgemm_body<false, true>(g_X, W, b, C, Xout, NNODES);
}

// ------------------------- whole layer: 3 routing iterations ---------------
__device__ __forceinline__ void decode16(uint4 r0, uint4 r1, float* f) {
    const __half2* hp = (const __half2*)&r0;
#pragma unroll
    for (int q = 0; q < 4; q++) {
        float2 t = __half22float2(hp[q]);
        f[2 * q] = t.x; f[2 * q + 1] = t.y;
    }
    const __half2* hq = (const __half2*)&r1;
#pragma unroll
    for (int q = 0; q < 4; q++) {
        float2 t = __half22float2(hq[q]);
        f[8 + 2 * q] = t.x; f[8 + 2 * q + 1] = t.y;
    }
}

template <int MODE, int BUF>
__global__ void __launch_bounds__(NWARPBLK * 32) k_layer() {
    extern __shared__ uint4 smz[];
    int wwarp = threadIdx.x >> 5;
    int v = blockIdx.x * NWARPBLK + wwarp;
    int lane = threadIdx.x & 31;
    if (v >= NNODES) return;
    int grp = lane >> 3;
    int sub = lane & 7;
    int half = sub & 1;
    const unsigned full = 0xffffffffu;
    const float LOG2E = 1.4426950408889634f;

    uint4* zc = smz + (size_t)wwarp * (CAP * 16);
    float* sbuf = ((float*)(smz + NWARPBLK * CAP * 16)) + wwarp * 32;

    int e0 = g_rowoff[v];
    int e1 = g_rowoff[v + 1];
    int nE = e1 - e0;
    int cached = nE < CAP ? nE : CAP;
    int niter = (nE + 3) >> 2;
    const uint4* XNH4 = (const uint4*)(BUF == 0 ? g_XNHA : g_XNHB);

    for (int idx = grp; idx < cached; idx += 4) {
        int u = __ldg(&g_csrc[e0 + idx]);
        uint4 a = __ldg(&XNH4[(size_t)u * 16 + sub * 2]);
        uint4 b = __ldg(&XNH4[(size_t)u * 16 + sub * 2 + 1]);
        zc[idx * 16 + sub * 2] = a;
        zc[idx * 16 + sub * 2 + 1] = b;
    }
    __syncwarp();

    float sv[16];
    {
        const float4* srow = (const float4*)(g_S + (size_t)v * 32 + half * 16);
#pragma unroll
        for (int q = 0; q < 4; q++) {
            float4 t = srow[q];
            sv[4 * q + 0] = t.x * LOG2E;
            sv[4 * q + 1] = t.y * LOG2E;
            sv[4 * q + 2] = t.z * LOG2E;
            sv[4 * q + 3] = t.w * LOG2E;
        }
    }

    const float4* xnrow = (const float4*)(g_XN + (size_t)v * DIM + sub * 16);

    for (int t = 0; t < ROUTIT; t++) {
        float acc[16];
        if (grp == 0) {
#pragma unroll
            for (int q = 0; q < 4; q++) {
                float4 tt = xnrow[q];
                acc[4 * q + 0] = tt.x; acc[4 * q + 1] = tt.y;
                acc[4 * q + 2] = tt.z; acc[4 * q + 3] = tt.w;
            }
        } else {
#pragma unroll
            for (int j = 0; j < 16; j++) acc[j] = 0.f;
        }

        for (int it = 0; it < niter; it++) {
            int idx = it * 4 + grp;
            bool valid = idx < nE;
            float f[16];
            if (idx < cached) {
                uint4 r0 = zc[idx * 16 + sub * 2];
                uint4 r1 = zc[idx * 16 + sub * 2 + 1];
                decode16(r0, r1, f);
            } else if (valid) {
                int u = __ldg(&g_csrc[e0 + idx]);
                uint4 r0 = __ldg(&XNH4[(size_t)u * 16 + sub * 2]);
                uint4 r1 = __ldg(&XNH4[(size_t)u * 16 + sub * 2 + 1]);
                decode16(r0, r1, f);
            } else {
#pragma unroll
                for (int j = 0; j < 16; j++) f[j] = 0.f;
            }

            float pd = 0.f;
#pragma unroll
            for (int j = 0; j < 16; j++) pd = fmaf(f[j], sv[j], pd);
            pd += __shfl_xor_sync(full, pd, 1);
            float ev = ex2(pd);
            float s2 = ev + __shfl_xor_sync(full, ev, 2);
            float denom = s2 + __shfl_xor_sync(full, s2, 4);
            float wgt = valid ? __fdividef(ev, denom) : 0.f;
#pragma unroll
            for (int j = 0; j < 16; j++) acc[j] = fmaf(wgt, f[j], acc[j]);
        }

#pragma unroll
        for (int j = 0; j < 16; j++) {
            acc[j] += __shfl_xor_sync(full, acc[j], 8);
            acc[j] += __shfl_xor_sync(full, acc[j], 16);
        }

        if (t < ROUTIT - 1) {
            float ss = 0.f;
#pragma unroll
            for (int j = 0; j < 16; j++) ss = fmaf(acc[j], acc[j], ss);
            ss += __shfl_xor_sync(full, ss, 1);
            float inv = 1.0f / fmaxf(sqrtf(ss), 1e-12f);
            if (grp == 0) {
                float4 qs;
                qs.x = (acc[0] + acc[1] + acc[2] + acc[3]) * inv;
                qs.y = (acc[4] + acc[5] + acc[6] + acc[7]) * inv;
                qs.z = (acc[8] + acc[9] + acc[10] + acc[11]) * inv;
                qs.w = (acc[12] + acc[13] + acc[14] + acc[15]) * inv;
                ((float4*)sbuf)[sub] = qs;
            }
            __syncwarp();
            const float4* srow = (const float4*)(sbuf + half * 16);
#pragma unroll
            for (int q = 0; q < 4; q++) {
                float4 tt = srow[q];
                sv[4 * q + 0] = tt.x * LOG2E;
                sv[4 * q + 1] = tt.y * LOG2E;
                sv[4 * q + 2] = tt.z * LOG2E;
                sv[4 * q + 3] = tt.w * LOG2E;
            }
            __syncwarp();
        } else if (grp == 0) {
            if (MODE == 2) {
                float4* o = (float4*)(g_X + (size_t)v * DIM + sub * 16);
#pragma unroll
                for (int q = 0; q < 4; q++)
                    o[q] = make_float4(acc[4 * q], acc[4 * q + 1],
                                       acc[4 * q + 2], acc[4 * q + 3]);
            } else {
                float ss = 0.f;
#pragma unroll
                for (int j = 0; j < 16; j++) ss = fmaf(acc[j], acc[j], ss);
                ss += __shfl_xor_sync(0xffu, ss, 1);
                float inv = 1.0f / fmaxf(sqrtf(ss), 1e-12f);
#pragma unroll
                for (int j = 0; j < 16; j++) acc[j] *= inv;
                float4 sout;
                sout.x = acc[0] + acc[1] + acc[2] + acc[3];
                sout.y = acc[4] + acc[5] + acc[6] + acc[7];
                sout.z = acc[8] + acc[9] + acc[10] + acc[11];
                sout.w = acc[12] + acc[13] + acc[14] + acc[15];
                ((float4*)(g_S + (size_t)v * 32))[sub] = sout;
                float4* xo = (float4*)(g_XN + (size_t)v * DIM + sub * 16);
                uint2* ho = g_XNHB + (size_t)v * 32 + sub * 4;
#pragma unroll
                for (int q = 0; q < 4; q++) {
                    xo[q] = make_float4(acc[4 * q], acc[4 * q + 1],
                                        acc[4 * q + 2], acc[4 * q + 3]);
                    __half2 h0 = __floats2half2_rn(acc[4 * q], acc[4 * q + 1]);
                    __half2 h1 = __floats2half2_rn(acc[4 * q + 2], acc[4 * q + 3]);
                    uint2 pk;
                    pk.x = *reinterpret_cast<unsigned int*>(&h0);
                    pk.y = *reinterpret_cast<unsigned int*>(&h1);
                    ho[q] = pk;
                }
            }
        }
    }
}

// ------------------------- launch -------------------------------------------
extern "C" void kernel_launch(void* const* d_in, const int* in_sizes, int n_in,
                              void* d_out, int out_size) {
    const float* feat  = (const float*)d_in[0];
    const void*  ei    = d_in[1];
    const float* lin_w = (const float*)d_in[2];
    const float* lin_b = (const float*)d_in[3];
    const float* mlp_w = (const float*)d_in[4];
    const float* mlp_b = (const float*)d_in[5];
    float* out = (float*)d_out;

    const int lsmem = NWARPBLK * CAP * 16 * 16 + NWARPBLK * 32 * 4;   // 66560
    cudaFuncSetAttribute(k_gemm_in,  cudaFuncAttributeMaxDynamicSharedMemorySize, TG_SMEM);
    cudaFuncSetAttribute(k_gemm_out, cudaFuncAttributeMaxDynamicSharedMemorySize, TG_SMEM);
    cudaFuncSetAttribute(k_layer<1, 0>, cudaFuncAttributeMaxDynamicSharedMemorySize, lsmem);
    cudaFuncSetAttribute(k_layer<2, 1>, cudaFuncAttributeMaxDynamicSharedMemorySize, lsmem);

    // 1: detect edge_index dtype (int32 vs int64)
    k_detect<<<1, 128>>>((const int*)ei);
    // 2-3: CSR histogram
    k_zero<<<(NNODES + 255) / 256, 256>>>();
    k_hist<<<(MEDGE + 255) / 256, 256>>>(ei);
    // 4: x = feat @ lin_w + lin_b (tensor cores), fused norm -> XN/XNHA/S
    k_gemm_in<<<TG_BLOCKS, TG_THREADS, TG_SMEM>>>(feat, lin_w, lin_b);
    // 5-7: finish CSR
    k_scan1<<<SCAN_NB, SCAN_BS>>>();
    k_scan3<<<(NNODES + 255) / 256, 256>>>();
    k_fill<<<(MEDGE + 255) / 256, 256>>>(ei);

    // 8: layer 1 (3 routing iterations; gathers A, publishes B)
    k_layer<1, 0><<<NODE_BLKS, NWARPBLK * 32, lsmem>>>();
    // 9: layer 2 (gathers B, writes raw c -> g_X)
    k_layer<2, 1><<<NODE_BLKS, NWARPBLK * 32, lsmem>>>();

    // 10: out = x @ mlp_w + mlp_b (tensor cores); also streams x to out[..]
    k_gemm_out<<<TG_BLOCKS, TG_THREADS, TG_SMEM>>>(mlp_w, mlp_b, out,
                                                   out + (size_t)NNODES * DIM);
}

// round 15
// speedup vs baseline: 1.3588x; 1.0009x over previous
#include <cuda_runtime.h>
#include <cuda_fp16.h>
#include <math.h>

#define NNODES 50000
#define DIM 128
#define MEDGE 800000
#define NWARPBLK 8
#define NODE_BLKS ((NNODES + NWARPBLK - 1) / NWARPBLK)   // 6250
#define SCAN_BS 1024
#define SCAN_NB ((NNODES + SCAN_BS - 1) / SCAN_BS)        // 49
#define CAP 16                                            // cached edges per node
#define ROUTIT 3

// tensor GEMM tiling
#define TG_ROWS 64
#define TG_THREADS 128
#define TG_STRIDE 136        // halves per smem row (128 + 8 pad)
#define TG_BLOCKS ((NNODES + TG_ROWS - 1) / TG_ROWS)      // 782
// smem half-offsets
#define OFF_AL (TG_ROWS * TG_STRIDE)                      // 8704
#define OFF_WH (2 * TG_ROWS * TG_STRIDE)                  // 17408
#define OFF_WL (OFF_WH + DIM * TG_STRIDE)                 // 34816
#define TG_SMEM ((OFF_WL + DIM * TG_STRIDE) * 2)          // 104448 bytes

// ------------------------- scratch (static device memory) -------------------
__device__ float g_X[NNODES * DIM];     // raw routing output (layer 2 only)
__device__ float g_XN[NNODES * DIM];    // normalized x, fp32 (self term)
__device__ uint2 g_XNHA[NNODES * 32];   // normalized x fp16, layer-1 gathers
__device__ uint2 g_XNHB[NNODES * 32];   // normalized x fp16, layer-2 gathers
__device__ float g_S[NNODES * 32];      // per-node s vector
__device__ int   g_deg[NNODES];
__device__ int   g_tmp[NNODES];
__device__ int   g_rowoff[NNODES + 1];
__device__ int   g_cursor[NNODES + 1];
__device__ int   g_csrc[MEDGE];
__device__ int   g_bsum[64];
__device__ int   g_is64;

__device__ __forceinline__ float ex2(float x) {
    float r;
    asm("ex2.approx.f32 %0, %1;" : "=f"(r) : "f"(x));
    return r;
}

__device__ __forceinline__ unsigned smem_u32(const void* p) {
    unsigned a;
    asm("{ .reg .u64 t; cvta.to.shared.u64 t, %1; cvt.u32.u64 %0, t; }"
        : "=r"(a) : "l"(p));
    return a;
}

__device__ __forceinline__ void ldmx4(unsigned* r, unsigned addr) {
    asm volatile("ldmatrix.sync.aligned.m8n8.x4.shared.b16 {%0,%1,%2,%3}, [%4];"
                 : "=r"(r[0]), "=r"(r[1]), "=r"(r[2]), "=r"(r[3]) : "r"(addr));
}
__device__ __forceinline__ void ldmx4t(unsigned* r, unsigned addr) {
    asm volatile("ldmatrix.sync.aligned.m8n8.x4.trans.shared.b16 {%0,%1,%2,%3}, [%4];"
                 : "=r"(r[0]), "=r"(r[1]), "=r"(r[2]), "=r"(r[3]) : "r"(addr));
}
__device__ __forceinline__ void mma16816(float* c, const unsigned* a, const unsigned* b) {
    asm volatile("mma.sync.aligned.m16n8k16.row.col.f32.f16.f16.f32 "
                 "{%0,%1,%2,%3}, {%4,%5,%6,%7}, {%8,%9}, {%0,%1,%2,%3};"
                 : "+f"(c[0]), "+f"(c[1]), "+f"(c[2]), "+f"(c[3])
                 : "r"(a[0]), "r"(a[1]), "r"(a[2]), "r"(a[3]), "r"(b[0]), "r"(b[1]));
}

// split a float pair into fp16 hi + fp16 residue
__device__ __forceinline__ void split2(float x, float y, __half2& h, __half2& l) {
    h = __floats2half2_rn(x, y);
    float2 hf = __half22float2(h);
    l = __floats2half2_rn(x - hf.x, y - hf.y);
}

// ------------------------- edge dtype probe + deg zero ----------------------
__global__ void k_detect(const int* __restrict__ ei) {
    int i = blockIdx.x * blockDim.x + threadIdx.x;
    if (i < NNODES) g_deg[i] = 0;
    if (blockIdx.x == 0) {
        __shared__ int nz;
        if (threadIdx.x == 0) nz = 0;
        __syncthreads();
        if (threadIdx.x < 128 && ei[2 * threadIdx.x + 1] != 0) atomicOr(&nz, 1);
        __syncthreads();
        if (threadIdx.x == 0) g_is64 = nz ? 0 : 1;
    }
}

__device__ __forceinline__ int load_idx(const void* ei, long long pos, int is64) {
    if (is64) return (int)((const long long*)ei)[pos];
    return ((const int*)ei)[pos];
}

// ------------------------- CSR build ----------------------------------------
__global__ void k_hist(const void* __restrict__ ei) {
    int e = blockIdx.x * blockDim.x + threadIdx.x;
    if (e < MEDGE) {
        int t = load_idx(ei, (long long)MEDGE + e, g_is64);
        atomicAdd(&g_deg[t], 1);
    }
}

__global__ void k_scan1() {
    __shared__ int wsum[32];
    const unsigned full = 0xffffffffu;
    int i = blockIdx.x * SCAN_BS + threadIdx.x;
    int lane = threadIdx.x & 31;
    int wid = threadIdx.x >> 5;
    int s = (i < NNODES) ? g_deg[i] : 0;
#pragma unroll
    for (int o = 1; o < 32; o <<= 1) {
        int t = __shfl_up_sync(full, s, o);
        if (lane >= o) s += t;
    }
    if (lane == 31) wsum[wid] = s;
    __syncthreads();
    if (wid == 0) {
        int w = wsum[lane];
#pragma unroll
        for (int o = 1; o < 32; o <<= 1) {
            int t = __shfl_up_sync(full, w, o);
            if (lane >= o) w += t;
        }
        wsum[lane] = w;
    }
    __syncthreads();
    int total = s + (wid ? wsum[wid - 1] : 0);
    if (i < NNODES) g_tmp[i] = total;
    if (threadIdx.x == SCAN_BS - 1) g_bsum[blockIdx.x] = total;
}

__global__ void k_scan3() {
    __shared__ int bx[SCAN_NB];
    if (threadIdx.x < SCAN_NB) bx[threadIdx.x] = g_bsum[threadIdx.x];
    __syncthreads();
    if (threadIdx.x == 0) {
        int run = 0;
#pragma unroll
        for (int b = 0; b < SCAN_NB; b++) { int t = bx[b]; bx[b] = run; run += t; }
    }
    __syncthreads();
    int i = blockIdx.x * blockDim.x + threadIdx.x;
    if (i < NNODES) {
        int inc = g_tmp[i] + bx[i >> 10];
        g_rowoff[i + 1] = inc;
        g_cursor[i + 1] = inc;
        if (i == 0) { g_rowoff[0] = 0; g_cursor[0] = 0; }
    }
}

__global__ void k_fill(const void* __restrict__ ei) {
    int e = blockIdx.x * blockDim.x + threadIdx.x;
    if (e < MEDGE) {
        int is64 = g_is64;
        int t = load_idx(ei, (long long)MEDGE + e, is64);
        int s = load_idx(ei, e, is64);
        int pos = atomicAdd(&g_cursor[t], 1);
        g_csrc[pos] = s;
    }
}

// --------------- tensor-core GEMM (rows x 128) @ (128 x 128) + bias ---------
// Split-fp16: X = Xh + Xl per operand; D = Ah*Wh + Ah*Wl + Al*Wh (fp32 acc).
template <bool NORM_EPI, bool COPY_A>
__device__ __forceinline__ void tgemm_body(const float* __restrict__ A,
                                           const float* __restrict__ W,
                                           const float* __restrict__ bias,
                                           float* __restrict__ C,
                                           float* __restrict__ Acopy, int nrows) {
    extern __shared__ __half smh[];
    const int tid = threadIdx.x;
    const int row0 = blockIdx.x * TG_ROWS;
    const unsigned full = 0xffffffffu;

    // ---- load W (128x128) as hi/lo fp16 splits ----
    const float4* W4 = (const float4*)W;
#pragma unroll
    for (int i = 0; i < 32; i++) {
        int idx = tid + i * TG_THREADS;
        int r = idx >> 5, c = idx & 31;
        float4 w = W4[r * 32 + c];
        __half2 h0, l0, h1, l1;
        split2(w.x, w.y, h0, l0);
        split2(w.z, w.w, h1, l1);
        int off = r * TG_STRIDE + c * 4;
        ((__half2*)(smh + OFF_WH + off))[0] = h0;
        ((__half2*)(smh + OFF_WH + off))[1] = h1;
        ((__half2*)(smh + OFF_WL + off))[0] = l0;
        ((__half2*)(smh + OFF_WL + off))[1] = l1;
    }
    // ---- load A tile (64x128) ----
    const float4* A4 = (const float4*)A;
#pragma unroll
    for (int i = 0; i < 16; i++) {
        int idx = tid + i * TG_THREADS;
        int r = idx >> 5, c = idx & 31;
        float4 a = make_float4(0.f, 0.f, 0.f, 0.f);
        if (row0 + r < nrows) {
            a = A4[(size_t)(row0 + r) * 32 + c];
            if (COPY_A) ((float4*)Acopy)[(size_t)(row0 + r) * 32 + c] = a;
        }
        __half2 h0, l0, h1, l1;
        split2(a.x, a.y, h0, l0);
        split2(a.z, a.w, h1, l1);
        int off = r * TG_STRIDE + c * 4;
        ((__half2*)(smh + off))[0] = h0;
        ((__half2*)(smh + off))[1] = h1;
        ((__half2*)(smh + OFF_AL + off))[0] = l0;
        ((__half2*)(smh + OFF_AL + off))[1] = l1;
    }
    __syncthreads();

    const int lane = tid & 31;
    const int warp = tid >> 5;
    const int m0 = warp * 16;

    unsigned sb = smem_u32(smh);
    unsigned aoff = (unsigned)((m0 + (lane & 15)) * TG_STRIDE + (lane >> 4) * 8) * 2;
    unsigned a_h = sb + aoff;
    unsigned a_l = sb + OFF_AL * 2 + aoff;
    // x4.trans B: lanes 0-15 -> rows k0-15 at col n0; lanes 16-31 -> col n0+8
    unsigned boff = (unsigned)((lane & 15) * TG_STRIDE + (lane >> 4) * 8) * 2;
    unsigned b_h0 = sb + OFF_WH * 2 + boff;
    unsigned b_l0 = sb + OFF_WL * 2 + boff;

    float acc[16][4];
#pragma unroll
    for (int t = 0; t < 16; t++)
#pragma unroll
        for (int j = 0; j < 4; j++) acc[t][j] = 0.f;

#pragma unroll
    for (int k = 0; k < 8; k++) {
        unsigned ah[4], al[4];
        ldmx4(ah, a_h + k * 32);
        ldmx4(al, a_l + k * 32);
        unsigned bk = (unsigned)(k * 16 * TG_STRIDE) * 2;
#pragma unroll
        for (int p = 0; p < 8; p++) {
            unsigned bh[4], bl[4];
            ldmx4t(bh, b_h0 + bk + p * 32);   // two n8 tiles: 2p, 2p+1
            ldmx4t(bl, b_l0 + bk + p * 32);
            mma16816(acc[2 * p],     ah, bh);
            mma16816(acc[2 * p],     ah, bl);
            mma16816(acc[2 * p],     al, bh);
            mma16816(acc[2 * p + 1], ah, bh + 2);
            mma16816(acc[2 * p + 1], ah, bl + 2);
            mma16816(acc[2 * p + 1], al, bh + 2);
        }
    }

    // ---- epilogue ----
    const int qr = lane >> 2;      // 0..7
    const int qc = lane & 3;       // 0..3
    int r0g = row0 + m0 + qr;      // rows for acc[.][0..1]
    int r1g = r0g + 8;             // rows for acc[.][2..3]

#pragma unroll
    for (int t = 0; t < 16; t++) {
        float2 bb = __ldg((const float2*)(bias + t * 8 + qc * 2));
        acc[t][0] += bb.x; acc[t][1] += bb.y;
        acc[t][2] += bb.x; acc[t][3] += bb.y;
    }

    if (!NORM_EPI) {
#pragma unroll
        for (int t = 0; t < 16; t++) {
            if (r0g < nrows)
                *(float2*)(C + (size_t)r0g * DIM + t * 8 + qc * 2) =
                    make_float2(acc[t][0], acc[t][1]);
            if (r1g < nrows)
                *(float2*)(C + (size_t)r1g * DIM + t * 8 + qc * 2) =
                    make_float2(acc[t][2], acc[t][3]);
        }
    } else {
        float ss0[4] = {0.f, 0.f, 0.f, 0.f};
        float ss1[4] = {0.f, 0.f, 0.f, 0.f};
#pragma unroll
        for (int t = 0; t < 16; t++) {
            int ch = t >> 2;
            ss0[ch] = fmaf(acc[t][0], acc[t][0], fmaf(acc[t][1], acc[t][1], ss0[ch]));
            ss1[ch] = fmaf(acc[t][2], acc[t][2], fmaf(acc[t][3], acc[t][3], ss1[ch]));
        }
        float inv0[4], inv1[4];
#pragma unroll
        for (int ch = 0; ch < 4; ch++) {
            float s0 = ss0[ch];
            s0 += __shfl_xor_sync(full, s0, 1);
            s0 += __shfl_xor_sync(full, s0, 2);
            inv0[ch] = 1.0f / fmaxf(sqrtf(s0), 1e-12f);
            float s1 = ss1[ch];
            s1 += __shfl_xor_sync(full, s1, 1);
            s1 += __shfl_xor_sync(full, s1, 2);
            inv1[ch] = 1.0f / fmaxf(sqrtf(s1), 1e-12f);
        }
        unsigned* XNHu = (unsigned*)g_XNHA;
#pragma unroll
        for (int t = 0; t < 16; t++) {
            int ch = t >> 2;
            float x0 = acc[t][0] * inv0[ch], y0 = acc[t][1] * inv0[ch];
            float x1 = acc[t][2] * inv1[ch], y1 = acc[t][3] * inv1[ch];
            float s0 = x0 + y0, s1 = x1 + y1;
            float p0 = __shfl_xor_sync(full, s0, 1);
            float p1 = __shfl_xor_sync(full, s1, 1);
            if (r0g < nrows) {
                *(float2*)(g_XN + (size_t)r0g * DIM + t * 8 + qc * 2) = make_float2(x0, y0);
                __half2 hh = __floats2half2_rn(x0, y0);
                XNHu[(size_t)r0g * 64 + t * 4 + qc] = *(unsigned*)&hh;
                if ((qc & 1) == 0) g_S[(size_t)r0g * 32 + t * 2 + (qc >> 1)] = s0 + p0;
            }
            if (r1g < nrows) {
                *(float2*)(g_XN + (size_t)r1g * DIM + t * 8 + qc * 2) = make_float2(x1, y1);
                __half2 hh = __floats2half2_rn(x1, y1);
                XNHu[(size_t)r1g * 64 + t * 4 + qc] = *(unsigned*)&hh;
                if ((qc & 1) == 0) g_S[(size_t)r1g * 32 + t * 2 + (qc >> 1)] = s1 + p1;
            }
        }
    }
}

__global__ void __launch_bounds__(TG_THREADS) k_gemm_in(const float* __restrict__ A,
                                                        const float* __restrict__ W,
                                                        const float* __restrict__ b) {
    tgemm_body<true, false>(A, W, b, nullptr, nullptr, NNODES);
}

__global__ void __launch_bounds__(TG_THREADS) k_gemm_out(const float* __restrict__ W,
                                                         const float* __restrict__ b,
                                                         float* __restrict__ C,
                                                         float* __restrict__ Xout) {
    tgemm_body<false, true>(g_X, W, b, C, Xout, NNODES);
}

// ------------------------- whole layer: 3 routing iterations ---------------
__device__ __forceinline__ void decode16(uint4 r0, uint4 r1, float* f) {
    const __half2* hp = (const __half2*)&r0;
#pragma unroll
    for (int q = 0; q < 4; q++) {
        float2 t = __half22float2(hp[q]);
        f[2 * q] = t.x; f[2 * q + 1] = t.y;
    }
    const __half2* hq = (const __half2*)&r1;
#pragma unroll
    for (int q = 0; q < 4; q++) {
        float2 t = __half22float2(hq[q]);
        f[8 + 2 * q] = t.x; f[8 + 2 * q + 1] = t.y;
    }
}

template <int MODE, int BUF>
__global__ void __launch_bounds__(NWARPBLK * 32) k_layer() {
    extern __shared__ uint4 smz[];
    int wwarp = threadIdx.x >> 5;
    int v = blockIdx.x * NWARPBLK + wwarp;
    int lane = threadIdx.x & 31;
    if (v >= NNODES) return;
    int grp = lane >> 3;
    int sub = lane & 7;
    int half = sub & 1;
    const unsigned full = 0xffffffffu;
    const float LOG2E = 1.4426950408889634f;

    uint4* zc = smz + (size_t)wwarp * (CAP * 16);
    float* sbuf = ((float*)(smz + NWARPBLK * CAP * 16)) + wwarp * 32;

    int e0 = g_rowoff[v];
    int e1 = g_rowoff[v + 1];
    int nE = e1 - e0;
    int cached = nE < CAP ? nE : CAP;
    int niter = (nE + 3) >> 2;
    const uint4* XNH4 = (const uint4*)(BUF == 0 ? g_XNHA : g_XNHB);

    for (int idx = grp; idx < cached; idx += 4) {
        int u = __ldg(&g_csrc[e0 + idx]);
        uint4 a = __ldg(&XNH4[(size_t)u * 16 + sub * 2]);
        uint4 b = __ldg(&XNH4[(size_t)u * 16 + sub * 2 + 1]);
        zc[idx * 16 + sub * 2] = a;
        zc[idx * 16 + sub * 2 + 1] = b;
    }
    __syncwarp();

    float sv[16];
    {
        const float4* srow = (const float4*)(g_S + (size_t)v * 32 + half * 16);
#pragma unroll
        for (int q = 0; q < 4; q++) {
            float4 t = srow[q];
            sv[4 * q + 0] = t.x * LOG2E;
            sv[4 * q + 1] = t.y * LOG2E;
            sv[4 * q + 2] = t.z * LOG2E;
            sv[4 * q + 3] = t.w * LOG2E;
        }
    }

    const float4* xnrow = (const float4*)(g_XN + (size_t)v * DIM + sub * 16);

    for (int t = 0; t < ROUTIT; t++) {
        float acc[16];
        if (grp == 0) {
#pragma unroll
            for (int q = 0; q < 4; q++) {
                float4 tt = xnrow[q];
                acc[4 * q + 0] = tt.x; acc[4 * q + 1] = tt.y;
                acc[4 * q + 2] = tt.z; acc[4 * q + 3] = tt.w;
            }
        } else {
#pragma unroll
            for (int j = 0; j < 16; j++) acc[j] = 0.f;
        }

        for (int it = 0; it < niter; it++) {
            int idx = it * 4 + grp;
            bool valid = idx < nE;
            float f[16];
            if (idx < cached) {
                uint4 r0 = zc[idx * 16 + sub * 2];
                uint4 r1 = zc[idx * 16 + sub * 2 + 1];
                decode16(r0, r1, f);
            } else if (valid) {
                int u = __ldg(&g_csrc[e0 + idx]);
                uint4 r0 = __ldg(&XNH4[(size_t)u * 16 + sub * 2]);
                uint4 r1 = __ldg(&XNH4[(size_t)u * 16 + sub * 2 + 1]);
                decode16(r0, r1, f);
            } else {
#pragma unroll
                for (int j = 0; j < 16; j++) f[j] = 0.f;
            }

            float pd = 0.f;
#pragma unroll
            for (int j = 0; j < 16; j++) pd = fmaf(f[j], sv[j], pd);
            pd += __shfl_xor_sync(full, pd, 1);
            float ev = ex2(pd);
            float s2 = ev + __shfl_xor_sync(full, ev, 2);
            float denom = s2 + __shfl_xor_sync(full, s2, 4);
            float wgt = valid ? __fdividef(ev, denom) : 0.f;
#pragma unroll
            for (int j = 0; j < 16; j++) acc[j] = fmaf(wgt, f[j], acc[j]);
        }

#pragma unroll
        for (int j = 0; j < 16; j++) {
            acc[j] += __shfl_xor_sync(full, acc[j], 8);
            acc[j] += __shfl_xor_sync(full, acc[j], 16);
        }

        if (t < ROUTIT - 1) {
            float ss = 0.f;
#pragma unroll
            for (int j = 0; j < 16; j++) ss = fmaf(acc[j], acc[j], ss);
            ss += __shfl_xor_sync(full, ss, 1);
            float inv = 1.0f / fmaxf(sqrtf(ss), 1e-12f);
            if (grp == 0) {
                float4 qs;
                qs.x = (acc[0] + acc[1] + acc[2] + acc[3]) * inv;
                qs.y = (acc[4] + acc[5] + acc[6] + acc[7]) * inv;
                qs.z = (acc[8] + acc[9] + acc[10] + acc[11]) * inv;
                qs.w = (acc[12] + acc[13] + acc[14] + acc[15]) * inv;
                ((float4*)sbuf)[sub] = qs;
            }
            __syncwarp();
            const float4* srow = (const float4*)(sbuf + half * 16);
#pragma unroll
            for (int q = 0; q < 4; q++) {
                float4 tt = srow[q];
                sv[4 * q + 0] = tt.x * LOG2E;
                sv[4 * q + 1] = tt.y * LOG2E;
                sv[4 * q + 2] = tt.z * LOG2E;
                sv[4 * q + 3] = tt.w * LOG2E;
            }
            __syncwarp();
        } else if (grp == 0) {
            if (MODE == 2) {
                float4* o = (float4*)(g_X + (size_t)v * DIM + sub * 16);
#pragma unroll
                for (int q = 0; q < 4; q++)
                    o[q] = make_float4(acc[4 * q], acc[4 * q + 1],
                                       acc[4 * q + 2], acc[4 * q + 3]);
            } else {
                float ss = 0.f;
#pragma unroll
                for (int j = 0; j < 16; j++) ss = fmaf(acc[j], acc[j], ss);
                ss += __shfl_xor_sync(0xffu, ss, 1);
                float inv = 1.0f / fmaxf(sqrtf(ss), 1e-12f);
#pragma unroll
                for (int j = 0; j < 16; j++) acc[j] *= inv;
                float4 sout;
                sout.x = acc[0] + acc[1] + acc[2] + acc[3];
                sout.y = acc[4] + acc[5] + acc[6] + acc[7];
                sout.z = acc[8] + acc[9] + acc[10] + acc[11];
                sout.w = acc[12] + acc[13] + acc[14] + acc[15];
                ((float4*)(g_S + (size_t)v * 32))[sub] = sout;
                float4* xo = (float4*)(g_XN + (size_t)v * DIM + sub * 16);
                uint2* ho = g_XNHB + (size_t)v * 32 + sub * 4;
#pragma unroll
                for (int q = 0; q < 4; q++) {
                    xo[q] = make_float4(acc[4 * q], acc[4 * q + 1],
                                        acc[4 * q + 2], acc[4 * q + 3]);
                    __half2 h0 = __floats2half2_rn(acc[4 * q], acc[4 * q + 1]);
                    __half2 h1 = __floats2half2_rn(acc[4 * q + 2], acc[4 * q + 3]);
                    uint2 pk;
                    pk.x = *reinterpret_cast<unsigned int*>(&h0);
                    pk.y = *reinterpret_cast<unsigned int*>(&h1);
                    ho[q] = pk;
                }
            }
        }
    }
}

// ------------------------- launch -------------------------------------------
extern "C" void kernel_launch(void* const* d_in, const int* in_sizes, int n_in,
                              void* d_out, int out_size) {
    const float* feat  = (const float*)d_in[0];
    const void*  ei    = d_in[1];
    const float* lin_w = (const float*)d_in[2];
    const float* lin_b = (const float*)d_in[3];
    const float* mlp_w = (const float*)d_in[4];
    const float* mlp_b = (const float*)d_in[5];
    float* out = (float*)d_out;

    const int lsmem = NWARPBLK * CAP * 16 * 16 + NWARPBLK * 32 * 4;   // 33792
    cudaFuncSetAttribute(k_gemm_in,  cudaFuncAttributeMaxDynamicSharedMemorySize, TG_SMEM);
    cudaFuncSetAttribute(k_gemm_out, cudaFuncAttributeMaxDynamicSharedMemorySize, TG_SMEM);
    cudaFuncSetAttribute(k_layer<1, 0>, cudaFuncAttributeMaxDynamicSharedMemorySize, lsmem);
    cudaFuncSetAttribute(k_layer<2, 1>, cudaFuncAttributeMaxDynamicSharedMemorySize, lsmem);

    // 1: dtype probe + zero degree array
    k_detect<<<(NNODES + 255) / 256, 256>>>((const int*)ei);
    // 2: CSR histogram
    k_hist<<<(MEDGE + 255) / 256, 256>>>(ei);
    // 3: x = feat @ lin_w + lin_b (tensor cores), fused norm -> XN/XNHA/S
    k_gemm_in<<<TG_BLOCKS, TG_THREADS, TG_SMEM>>>(feat, lin_w, lin_b);
    // 4-6: finish CSR
    k_scan1<<<SCAN_NB, SCAN_BS>>>();
    k_scan3<<<(NNODES + 255) / 256, 256>>>();
    k_fill<<<(MEDGE + 255) / 256, 256>>>(ei);

    // 7: layer 1 (3 routing iterations; gathers A, publishes B)
    k_layer<1, 0><<<NODE_BLKS, NWARPBLK * 32, lsmem>>>();
    // 8: layer 2 (gathers B, writes raw c -> g_X)
    k_layer<2, 1><<<NODE_BLKS, NWARPBLK * 32, lsmem>>>();

    // 9: out = x @ mlp_w + mlp_b (tensor cores); also streams x to out[..]
    k_gemm_out<<<TG_BLOCKS, TG_THREADS, TG_SMEM>>>(mlp_w, mlp_b, out,
                                                   out + (size_t)NNODES * DIM);
}